// round 4
// baseline (speedup 1.0000x reference)
#include <cuda_runtime.h>
#include <math.h>

#define BB 256
#define TT 128
#define HH 256
#define FF 16
#define GG 1040   // 4*H + F

typedef unsigned long long u64;

// ---- static device scratch ----
__device__ float g_xproj[TT * GG * BB];   // [t][g][b]
__device__ float g_h[2][HH * BB];         // [j][b], double buffered
__device__ unsigned g_bar;                // grid barrier counter

__device__ __forceinline__ float hsig(float x) {
    return __saturatef(x * 0.16666667f + 0.5f);
}
__device__ __forceinline__ float ftanh(float x) {
    // tanh(x) = 1 - 2/(e^{2x}+1); MUFU-based, ~1e-6 abs err
    float e = __expf(2.0f * x);
    return 1.0f - __fdividef(2.0f, e + 1.0f);
}
__device__ __forceinline__ void fma2(u64& d, u64 a, u64 b) {
    asm("fma.rn.f32x2 %0, %1, %2, %0;" : "+l"(d) : "l"(a), "l"(b));
}
__device__ __forceinline__ void upk2(float& lo, float& hi, u64 v) {
    asm("mov.b64 {%0, %1}, %2;" : "=f"(lo), "=f"(hi) : "l"(v));
}

// ---------------- init ----------------
__global__ void init_kernel() {
    int i = blockIdx.x * blockDim.x + threadIdx.x;
    int n = blockDim.x * gridDim.x;
    for (int k = i; k < 2 * HH * BB; k += n) (&g_h[0][0])[k] = 0.f;
    if (i == 0) g_bar = 0u;
}

// ---------------- phase 0: input projection ----------------
// xproj[t][g][b] = sum_k X[b,t,k] * W[k,g] + bias[g]
// grid (17 g-tiles of 64, 4 b-tiles of 64, 128 t), 128 threads
__global__ void proj_kernel(
    const float* __restrict__ sig, const float* __restrict__ met,
    const float* __restrict__ Wis, const float* __restrict__ Wss, const float* __restrict__ Wfs,
    const float* __restrict__ Wcs, const float* __restrict__ Wos,
    const float* __restrict__ Wim, const float* __restrict__ Wsm, const float* __restrict__ Wfm,
    const float* __restrict__ Wcm, const float* __restrict__ Wom,
    const float* __restrict__ b_i, const float* __restrict__ b_ste, const float* __restrict__ b_fre,
    const float* __restrict__ b_c, const float* __restrict__ b_o)
{
    __shared__ u64   A2_s[96 * 66];   // [k][b] duplicated {v,v}, stride 66
    __shared__ float B_s[96 * 64];    // [k][n]
    const int n0 = blockIdx.x * 64;
    const int b0 = blockIdx.y * 64;
    const int t  = blockIdx.z;
    const int tid = threadIdx.x;

    for (int idx = tid; idx < 64 * 96; idx += 128) {
        int b = idx / 96, k = idx - b * 96;
        float v = (k < 64) ? sig[((b0 + b) * TT + t) * 64 + k]
                           : met[((b0 + b) * TT + t) * 32 + (k - 64)];
        *(float2*)&A2_s[k * 66 + b] = make_float2(v, v);
    }
    for (int idx = tid; idx < 96 * 64; idx += 128) {
        int k = idx >> 6, n = idx & 63;
        int g = n0 + n;
        float v = 0.f;
        if (g < 1024) {
            int gate = g >> 8, j = g & 255;
            const float* Ws = (gate == 0) ? Wis : (gate == 1) ? Wss : (gate == 2) ? Wcs : Wos;
            const float* Wm = (gate == 0) ? Wim : (gate == 1) ? Wsm : (gate == 2) ? Wcm : Wom;
            v = (k < 64) ? Ws[k * 256 + j] : Wm[(k - 64) * 256 + j];
        } else if (g < GG) {
            int f = g - 1024;
            v = (k < 64) ? Wfs[k * 16 + f] : Wfm[(k - 64) * 16 + f];
        }
        B_s[k * 64 + n] = v;
    }
    __syncthreads();

    // 16 b-groups (4 b each) x 8 g-groups (8 g each)
    const int tm = tid >> 3, tn = tid & 7;
    const int mb = tm * 4, nb = tn * 8;
    u64 acc2[4][4] = {};
    for (int k = 0; k < 96; k++) {
        ulonglong2 a01 = *(const ulonglong2*)(A2_s + k * 66 + mb);     // {a0,a0},{a1,a1}
        ulonglong2 a23 = *(const ulonglong2*)(A2_s + k * 66 + mb + 2); // {a2,a2},{a3,a3}
        ulonglong2 bA = *(const ulonglong2*)(B_s + k * 64 + nb);       // {b0,b1},{b2,b3}
        ulonglong2 bB = *(const ulonglong2*)(B_s + k * 64 + nb + 4);   // {b4,b5},{b6,b7}
        fma2(acc2[0][0], a01.x, bA.x); fma2(acc2[0][1], a01.x, bA.y);
        fma2(acc2[0][2], a01.x, bB.x); fma2(acc2[0][3], a01.x, bB.y);
        fma2(acc2[1][0], a01.y, bA.x); fma2(acc2[1][1], a01.y, bA.y);
        fma2(acc2[1][2], a01.y, bB.x); fma2(acc2[1][3], a01.y, bB.y);
        fma2(acc2[2][0], a23.x, bA.x); fma2(acc2[2][1], a23.x, bA.y);
        fma2(acc2[2][2], a23.x, bB.x); fma2(acc2[2][3], a23.x, bB.y);
        fma2(acc2[3][0], a23.y, bA.x); fma2(acc2[3][1], a23.y, bA.y);
        fma2(acc2[3][2], a23.y, bB.x); fma2(acc2[3][3], a23.y, bB.y);
    }
    float r[4][8];
#pragma unroll
    for (int bi = 0; bi < 4; bi++)
#pragma unroll
        for (int gp = 0; gp < 4; gp++)
            upk2(r[bi][gp * 2], r[bi][gp * 2 + 1], acc2[bi][gp]);
#pragma unroll
    for (int gq = 0; gq < 8; gq++) {
        int g = n0 + nb + gq;
        if (g >= GG) continue;
        float bias;
        if (g < 1024) {
            int gate = g >> 8, j = g & 255;
            bias = (gate == 0) ? b_i[j] : (gate == 1) ? b_ste[j] : (gate == 2) ? b_c[j] : b_o[j];
        } else {
            bias = b_fre[g - 1024];
        }
        float4 w;
        w.x = r[0][gq] + bias; w.y = r[1][gq] + bias;
        w.z = r[2][gq] + bias; w.w = r[3][gq] + bias;
        *(float4*)&g_xproj[(t * GG + g) * BB + b0 + mb] = w;
    }
}

// ---------------- persistent recurrence kernel ----------------
// 128 CTAs (8 b-tiles x 16 j-tiles), 256 threads, all 128 steps in one launch.
// smem layout (floats):
#define PS_U    0                       // [k=256][80]: cols 0-63 gates (gate*16+jj), 64-79 fre
#define PS_H2   (PS_U + 256 * 80)       // [k=256][34] u64 {h,h} duplicated
#define PS_GT   (PS_H2 + 256 * 34 * 2)  // [80][33]  GEMM outputs [g][b]
#define PS_X    (PS_GT + 80 * 33)       // [2560]    xproj slice: gates 2048 + fre 512
#define PS_RE   (PS_X + 2560)
#define PS_IM   (PS_RE + 16)
#define PS_UA   (PS_IM + 16)
#define PS_BA   (PS_UA + 16)
#define PS_TOTAL (PS_BA + 16)

__global__ void __launch_bounds__(256, 1) persist_kernel(
    const float* __restrict__ U_i, const float* __restrict__ U_ste,
    const float* __restrict__ U_c, const float* __restrict__ U_o,
    const float* __restrict__ U_fre, const float* __restrict__ U_a,
    const float* __restrict__ b_a)
{
    extern __shared__ float sm[];
    float* U_s  = sm + PS_U;
    u64*   h2_s = (u64*)(sm + PS_H2);
    float* gt_s = sm + PS_GT;
    float* x_s  = sm + PS_X;
    float* re_s = sm + PS_RE;
    float* im_s = sm + PS_IM;
    float* Ua_s = sm + PS_UA;
    float* ba_s = sm + PS_BA;

    const int tid = threadIdx.x;
    const int bt = blockIdx.x & 7, jt = blockIdx.x >> 3;
    const int b0 = bt * 32, j0 = jt * 16;

    // ---- one-time staging of U columns ----
    for (int idx = tid; idx < 256 * 64; idx += 256) {
        int k = idx >> 6, g = idx & 63;
        int gate = g >> 4, jj = g & 15;
        const float* U = (gate == 0) ? U_i : (gate == 1) ? U_ste : (gate == 2) ? U_c : U_o;
        U_s[k * 80 + g] = U[k * 256 + j0 + jj];
    }
    for (int idx = tid; idx < 256 * 16; idx += 256) {
        int k = idx >> 4, f = idx & 15;
        U_s[k * 80 + 64 + f] = U_fre[k * 16 + f];
    }
    if (tid < 16) { Ua_s[tid] = U_a[tid]; ba_s[tid] = b_a[j0 + tid]; }

    // ---- S state in registers: 2 (b,j) pairs x 16 f ----
    float Sre[2][16], Sim[2][16];
#pragma unroll
    for (int p = 0; p < 2; p++)
#pragma unroll
        for (int f = 0; f < 16; f++) { Sre[p][f] = 0.f; Sim[p][f] = 0.f; }

    const int c_jj = tid >> 4;   // consumer j within tile
    const int c_b  = tid & 15;   // consumer base b

    for (int t = 0; t < TT; t++) {
        // ---- stage h duplicated {h,h} (L2-only loads) ----
        const float* hin = &g_h[t & 1][0];
        for (int idx = tid; idx < 256 * 32; idx += 256) {
            int b = idx & 31, k = idx >> 5;
            float v = __ldcg(&hin[k * 256 + b0 + b]);
            *(float2*)&h2_s[k * 34 + b] = make_float2(v, v);
        }
        __syncthreads();

        if (tid < 128) {
            // ---- gates GEMM: 32b x 64g; per thread 2b x 8g via FFMA2 ----
            const int bg = tid >> 3;   // 0..15 -> b pair at bg*2
            const int gg = tid & 7;    // 0..7  -> 8 g at gg*8
            const u64*  hp = h2_s + bg * 2;
            const float* up = U_s + gg * 8;
            u64 acc2[2][4] = {};
#pragma unroll 4
            for (int k = 0; k < 256; k++) {
                ulonglong2 hv = *(const ulonglong2*)(hp + k * 34);   // {h0,h0},{h1,h1}
                ulonglong2 u01 = *(const ulonglong2*)(up + k * 80);      // {u0,u1},{u2,u3}
                ulonglong2 u23 = *(const ulonglong2*)(up + k * 80 + 4);  // {u4,u5},{u6,u7}
                fma2(acc2[0][0], hv.x, u01.x); fma2(acc2[0][1], hv.x, u01.y);
                fma2(acc2[0][2], hv.x, u23.x); fma2(acc2[0][3], hv.x, u23.y);
                fma2(acc2[1][0], hv.y, u01.x); fma2(acc2[1][1], hv.y, u01.y);
                fma2(acc2[1][2], hv.y, u23.x); fma2(acc2[1][3], hv.y, u23.y);
            }
#pragma unroll
            for (int bl = 0; bl < 2; bl++)
#pragma unroll
                for (int gp = 0; gp < 4; gp++) {
                    float lo, hi;
                    upk2(lo, hi, acc2[bl][gp]);
                    int g = gg * 8 + gp * 2;
                    int b = bg * 2 + bl;
                    gt_s[g * 33 + b] = lo;
                    gt_s[(g + 1) * 33 + b] = hi;
                }
        } else {
            const int s = tid - 128;
            // ---- prefetch this step's xproj slice (DRAM) into smem ----
            const int xt = t * GG * BB;
            for (int idx = s; idx < 2048; idx += 128) {
                int gate = idx >> 9, jj = (idx >> 5) & 15, b = idx & 31;
                x_s[idx] = g_xproj[xt + (gate * 256 + j0 + jj) * BB + b0 + b];
            }
            for (int idx = s; idx < 512; idx += 128) {
                int f = idx >> 5, b = idx & 31;
                x_s[2048 + idx] = g_xproj[xt + (1024 + f) * BB + b0 + b];
            }
            if (s < 16) {
                float ang = 6.2831855f * (float)(t + 1) * ((float)s * 0.0625f);
                float sv, cv;
                sincosf(ang, &sv, &cv);
                re_s[s] = cv; im_s[s] = sv;
            }
            // ---- fre matvec: 32b x 16f; per thread 1b x 4f via FFMA2 ----
            const int fb = s >> 2, f0 = (s & 3) * 4;
            const float* up = U_s + 64 + f0;
            u64 af2[2] = {};
#pragma unroll 4
            for (int k = 0; k < 256; k++) {
                u64 hsp = h2_s[k * 34 + fb];                          // {h,h}
                ulonglong2 uf = *(const ulonglong2*)(up + k * 80);    // {u0,u1},{u2,u3}
                fma2(af2[0], hsp, uf.x);
                fma2(af2[1], hsp, uf.y);
            }
            float fa0, fa1, fa2, fa3;
            upk2(fa0, fa1, af2[0]);
            upk2(fa2, fa3, af2[1]);
            gt_s[(64 + f0 + 0) * 33 + fb] = fa0;
            gt_s[(64 + f0 + 1) * 33 + fb] = fa1;
            gt_s[(64 + f0 + 2) * 33 + fb] = fa2;
            gt_s[(64 + f0 + 3) * 33 + fb] = fa3;
        }
        __syncthreads();

        // ---- consumer: S update (registers) + h output ----
        float* hout = &g_h[(t & 1) ^ 1][0];
#pragma unroll
        for (int p = 0; p < 2; p++) {
            const int b = c_b + p * 16;
            float gi  = hsig(gt_s[(     c_jj) * 33 + b] + x_s[(     c_jj) * 32 + b]);
            float ste = hsig(gt_s[(16 + c_jj) * 33 + b] + x_s[(16 + c_jj) * 32 + b]);
            float cg  = gi * ftanh(gt_s[(32 + c_jj) * 33 + b] + x_s[(32 + c_jj) * 32 + b]);
            float o   = hsig(gt_s[(48 + c_jj) * 33 + b] + x_s[(48 + c_jj) * 32 + b]);
            float Aa = 0.f;
#pragma unroll
            for (int f = 0; f < 16; f++) {
                float fre = hsig(gt_s[(64 + f) * 33 + b] + x_s[2048 + f * 32 + b]);
                float fv = ste * fre;
                float nr = fv * Sre[p][f] + cg * re_s[f];
                float ni = fv * Sim[p][f] + cg * im_s[f];
                Sre[p][f] = nr; Sim[p][f] = ni;
                Aa += (nr * nr + ni * ni) * Ua_s[f];
            }
            float a = ftanh(Aa + ba_s[c_jj]);
            __stcg(&hout[(j0 + c_jj) * 256 + b0 + b], o * a);
        }

        // ---- grid barrier: atomic arrive, volatile-load poll ----
        __threadfence();
        __syncthreads();
        if (tid == 0) {
            atomicAdd(&g_bar, 1u);
            const unsigned target = 128u * (unsigned)(t + 1);
            while (*(volatile unsigned*)&g_bar < target) { }
        }
        __syncthreads();
    }
}

// ---------------- output head ----------------
__global__ void final_kernel(const float* __restrict__ W_p, const float* __restrict__ b_p,
                             const float* __restrict__ fc_w, const float* __restrict__ fc_b,
                             float* __restrict__ out)
{
    int b = threadIdx.x;
    const float* h = &g_h[0][0];   // after 128 steps (t=127 writes buf 0)
    float s = 0.f;
    for (int j = 0; j < 256; j++) s += h[j * 256 + b] * W_p[j];
    float p = s + b_p[0];
    out[b] = p * fc_w[0] + fc_b[0];
}

// ---------------- launch ----------------
extern "C" void kernel_launch(void* const* d_in, const int* in_sizes, int n_in,
                              void* d_out, int out_size)
{
    const float* sig  = (const float*)d_in[0];
    const float* met  = (const float*)d_in[1];
    const float* Wis  = (const float*)d_in[2];
    const float* Wss  = (const float*)d_in[3];
    const float* Wfs  = (const float*)d_in[4];
    const float* Wcs  = (const float*)d_in[5];
    const float* Wos  = (const float*)d_in[6];
    const float* Wim  = (const float*)d_in[7];
    const float* Wsm  = (const float*)d_in[8];
    const float* Wfm  = (const float*)d_in[9];
    const float* Wcm  = (const float*)d_in[10];
    const float* Wom  = (const float*)d_in[11];
    const float* U_i  = (const float*)d_in[12];
    const float* b_i  = (const float*)d_in[13];
    const float* U_ste= (const float*)d_in[14];
    const float* b_ste= (const float*)d_in[15];
    const float* U_fre= (const float*)d_in[16];
    const float* b_fre= (const float*)d_in[17];
    const float* U_c  = (const float*)d_in[18];
    const float* b_c  = (const float*)d_in[19];
    const float* U_o  = (const float*)d_in[20];
    const float* b_o  = (const float*)d_in[21];
    const float* U_a  = (const float*)d_in[22];
    const float* b_a  = (const float*)d_in[23];
    const float* W_p  = (const float*)d_in[24];
    const float* b_p  = (const float*)d_in[25];
    const float* fc_w = (const float*)d_in[26];
    const float* fc_b = (const float*)d_in[27];
    float* out = (float*)d_out;

    cudaFuncSetAttribute(persist_kernel, cudaFuncAttributeMaxDynamicSharedMemorySize,
                         PS_TOTAL * 4);

    init_kernel<<<148, 256>>>();
    proj_kernel<<<dim3(17, 4, 128), 128>>>(sig, met, Wis, Wss, Wfs, Wcs, Wos,
                                           Wim, Wsm, Wfm, Wcm, Wom,
                                           b_i, b_ste, b_fre, b_c, b_o);
    persist_kernel<<<128, 256, PS_TOTAL * 4>>>(U_i, U_ste, U_c, U_o, U_fre, U_a, b_a);
    final_kernel<<<1, 256>>>(W_p, b_p, fc_w, fc_b, out);
}

// round 5
// speedup vs baseline: 1.4970x; 1.4970x over previous
#include <cuda_runtime.h>
#include <math.h>

#define BB 256
#define TT 128
#define HH 256
#define FF 16
#define GG 1040   // 4*H + F

// ---- static device scratch ----
__device__ float g_xproj[TT * GG * BB];   // [t][g][b]
__device__ float g_h[2][HH * BB];         // [j][b], double buffered (never needs init)
__device__ unsigned g_bar;                // grid barrier counter

__device__ __forceinline__ float hsig(float x) {
    return __saturatef(x * 0.16666667f + 0.5f);
}
__device__ __forceinline__ float ftanh(float x) {
    float e = __expf(2.0f * x);
    return 1.0f - __fdividef(2.0f, e + 1.0f);
}

// ---------------- init: reset barrier only ----------------
__global__ void init_kernel() {
    g_bar = 0u;
}

// ---------------- phase 0: input projection (round-3 proven version) ----------------
// xproj[t][g][b] = sum_k X[b,t,k] * W[k,g] + bias[g]
__global__ void proj_kernel(
    const float* __restrict__ sig, const float* __restrict__ met,
    const float* __restrict__ Wis, const float* __restrict__ Wss, const float* __restrict__ Wfs,
    const float* __restrict__ Wcs, const float* __restrict__ Wos,
    const float* __restrict__ Wim, const float* __restrict__ Wsm, const float* __restrict__ Wfm,
    const float* __restrict__ Wcm, const float* __restrict__ Wom,
    const float* __restrict__ b_i, const float* __restrict__ b_ste, const float* __restrict__ b_fre,
    const float* __restrict__ b_c, const float* __restrict__ b_o)
{
    __shared__ float A_s[96 * 64];   // [k][b]
    __shared__ float B_s[96 * 64];   // [k][n]
    const int n0 = blockIdx.x * 64;
    const int b0 = blockIdx.y * 64;
    const int t  = blockIdx.z;
    const int tid = threadIdx.x;

    for (int idx = tid; idx < 64 * 96; idx += 128) {
        int b = idx / 96, k = idx - b * 96;
        float v = (k < 64) ? sig[((b0 + b) * TT + t) * 64 + k]
                           : met[((b0 + b) * TT + t) * 32 + (k - 64)];
        A_s[k * 64 + b] = v;
    }
    for (int idx = tid; idx < 96 * 64; idx += 128) {
        int k = idx >> 6, n = idx & 63;
        int g = n0 + n;
        float v = 0.f;
        if (g < 1024) {
            int gate = g >> 8, j = g & 255;
            const float* Ws = (gate == 0) ? Wis : (gate == 1) ? Wss : (gate == 2) ? Wcs : Wos;
            const float* Wm = (gate == 0) ? Wim : (gate == 1) ? Wsm : (gate == 2) ? Wcm : Wom;
            v = (k < 64) ? Ws[k * 256 + j] : Wm[(k - 64) * 256 + j];
        } else if (g < GG) {
            int f = g - 1024;
            v = (k < 64) ? Wfs[k * 16 + f] : Wfm[(k - 64) * 16 + f];
        }
        B_s[k * 64 + n] = v;
    }
    __syncthreads();

    const int tm = tid & 7, tn = tid >> 3;
    const int mb = tm * 8, nb = tn * 4;
    float acc[8][4] = {};
    for (int k = 0; k < 96; k++) {
        float4 a0 = *(const float4*)&A_s[k * 64 + mb];
        float4 a1 = *(const float4*)&A_s[k * 64 + mb + 4];
        float4 bv = *(const float4*)&B_s[k * 64 + nb];
        float am[8] = {a0.x, a0.y, a0.z, a0.w, a1.x, a1.y, a1.z, a1.w};
#pragma unroll
        for (int i = 0; i < 8; i++) {
            acc[i][0] += am[i] * bv.x; acc[i][1] += am[i] * bv.y;
            acc[i][2] += am[i] * bv.z; acc[i][3] += am[i] * bv.w;
        }
    }
#pragma unroll
    for (int q = 0; q < 4; q++) {
        int g = n0 + nb + q;
        if (g >= GG) continue;
        float bias;
        if (g < 1024) {
            int gate = g >> 8, j = g & 255;
            bias = (gate == 0) ? b_i[j] : (gate == 1) ? b_ste[j] : (gate == 2) ? b_c[j] : b_o[j];
        } else {
            bias = b_fre[g - 1024];
        }
        float4 w0, w1;
        w0.x = acc[0][q] + bias; w0.y = acc[1][q] + bias;
        w0.z = acc[2][q] + bias; w0.w = acc[3][q] + bias;
        w1.x = acc[4][q] + bias; w1.y = acc[5][q] + bias;
        w1.z = acc[6][q] + bias; w1.w = acc[7][q] + bias;
        float* dst = &g_xproj[(t * GG + g) * BB + b0 + mb];
        *(float4*)dst = w0;
        *(float4*)(dst + 4) = w1;
    }
}

// ---------------- persistent recurrence kernel ----------------
// 128 CTAs (8 b-tiles x 16 j-tiles), 256 threads, all 128 steps + final head.
#define PS_U     0                        // [k=256][80]: 0-63 gates (gate*16+jj), 64-79 fre
#define PS_H     (PS_U + 256 * 80)        // [k=256][36]
#define PS_GT    (PS_H + 256 * 36)        // [80][33]  GEMM outputs [g][b]
#define PS_X     (PS_GT + 80 * 33)        // 2 x [80][33] xproj double buffer
#define PS_RE    (PS_X + 2 * 80 * 33)     // [128][16] cos table
#define PS_IM    (PS_RE + 2048)           // [128][16] sin table
#define PS_UA    (PS_IM + 2048)
#define PS_BA    (PS_UA + 16)
#define PS_TOTAL (PS_BA + 16)

__global__ void __launch_bounds__(256, 1) persist_kernel(
    const float* __restrict__ U_i, const float* __restrict__ U_ste,
    const float* __restrict__ U_c, const float* __restrict__ U_o,
    const float* __restrict__ U_fre, const float* __restrict__ U_a,
    const float* __restrict__ b_a,
    const float* __restrict__ W_p, const float* __restrict__ b_p,
    const float* __restrict__ fc_w, const float* __restrict__ fc_b,
    float* __restrict__ out)
{
    extern __shared__ float sm[];
    float* U_s  = sm + PS_U;
    float* h_s  = sm + PS_H;
    float* gt_s = sm + PS_GT;
    float* x_s  = sm + PS_X;          // two buffers of 80*33
    float* re_t = sm + PS_RE;
    float* im_t = sm + PS_IM;
    float* Ua_s = sm + PS_UA;
    float* ba_s = sm + PS_BA;

    const int tid = threadIdx.x;
    const int bt = blockIdx.x & 7, jt = blockIdx.x >> 3;
    const int b0 = bt * 32, j0 = jt * 16;

    // ---- one-time staging ----
    for (int idx = tid; idx < 256 * 64; idx += 256) {
        int k = idx >> 6, g = idx & 63;
        int gate = g >> 4, jj = g & 15;
        const float* U = (gate == 0) ? U_i : (gate == 1) ? U_ste : (gate == 2) ? U_c : U_o;
        U_s[k * 80 + g] = U[k * 256 + j0 + jj];
    }
    for (int idx = tid; idx < 256 * 16; idx += 256) {
        int k = idx >> 4, f = idx & 15;
        U_s[k * 80 + 64 + f] = U_fre[k * 16 + f];
    }
    // sincos table for all steps
    for (int idx = tid; idx < TT * 16; idx += 256) {
        int tt = idx >> 4, f = idx & 15;
        float ang = 6.2831855f * (float)(tt + 1) * ((float)f * 0.0625f);
        float sv, cv;
        sincosf(ang, &sv, &cv);
        re_t[idx] = cv; im_t[idx] = sv;
    }
    if (tid < 16) { Ua_s[tid] = U_a[tid]; ba_s[tid] = b_a[j0 + tid]; }

    // ---- prefetch xproj for t=0 into buffer 0 ----
    {
        const int xt = 0;
        for (int idx = tid; idx < 2048; idx += 256) {
            int gate = idx >> 9, jj = (idx >> 5) & 15, b = idx & 31;
            x_s[(gate * 16 + jj) * 33 + b] = g_xproj[xt + (gate * 256 + j0 + jj) * BB + b0 + b];
        }
        for (int idx = tid; idx < 512; idx += 256) {
            int f = idx >> 5, b = idx & 31;
            x_s[(64 + f) * 33 + b] = g_xproj[xt + (1024 + f) * BB + b0 + b];
        }
    }

    // ---- S state in registers: 2 consecutive b x 16 f ----
    float Sre[2][16], Sim[2][16];
#pragma unroll
    for (int p = 0; p < 2; p++)
#pragma unroll
        for (int f = 0; f < 16; f++) { Sre[p][f] = 0.f; Sim[p][f] = 0.f; }

    const int c_jj = tid >> 4;          // 0..15
    const int c_b2 = (tid & 15) * 2;    // consecutive b pair

    for (int t = 0; t < TT; t++) {
        // ---- stage h (float4 ldcg; zeros at t=0) ----
        if (t == 0) {
            const float4 z = make_float4(0.f, 0.f, 0.f, 0.f);
            for (int idx = tid; idx < 2048; idx += 256) {
                int k = idx >> 3, q = idx & 7;
                *(float4*)&h_s[k * 36 + q * 4] = z;
            }
        } else {
            const float* hin = &g_h[t & 1][0];
            for (int idx = tid; idx < 2048; idx += 256) {
                int k = idx >> 3, q = idx & 7;
                float4 v = __ldcg((const float4*)&hin[k * 256 + b0 + q * 4]);
                *(float4*)&h_s[k * 36 + q * 4] = v;
            }
        }
        __syncthreads();

        float* xc = x_s + (t & 1) * (80 * 33);        // consume buffer
        float* xn = x_s + ((t + 1) & 1) * (80 * 33);  // prefetch buffer

        if (tid < 128) {
            // ---- gates GEMM: 32b x 64g, 4b x 4g per thread ----
            const int bg = tid >> 4, gg = tid & 15;
            const float* hp = h_s + bg * 4;
            const float* up = U_s + gg * 4;
            float acc[4][4] = {};
#pragma unroll 4
            for (int k = 0; k < 256; k++) {
                float4 hv = *(const float4*)(hp + k * 36);
                float4 uv = *(const float4*)(up + k * 80);
                acc[0][0] += hv.x * uv.x; acc[0][1] += hv.x * uv.y; acc[0][2] += hv.x * uv.z; acc[0][3] += hv.x * uv.w;
                acc[1][0] += hv.y * uv.x; acc[1][1] += hv.y * uv.y; acc[1][2] += hv.y * uv.z; acc[1][3] += hv.y * uv.w;
                acc[2][0] += hv.z * uv.x; acc[2][1] += hv.z * uv.y; acc[2][2] += hv.z * uv.z; acc[2][3] += hv.z * uv.w;
                acc[3][0] += hv.w * uv.x; acc[3][1] += hv.w * uv.y; acc[3][2] += hv.w * uv.z; acc[3][3] += hv.w * uv.w;
            }
#pragma unroll
            for (int q = 0; q < 4; q++)
#pragma unroll
                for (int i = 0; i < 4; i++)
                    gt_s[(gg * 4 + q) * 33 + bg * 4 + i] = acc[i][q];
        } else {
            const int s = tid - 128;
            // ---- prefetch next step's xproj (independent of h) ----
            if (t + 1 < TT) {
                const int xt = (t + 1) * GG * BB;
                for (int idx = s; idx < 2048; idx += 128) {
                    int gate = idx >> 9, jj = (idx >> 5) & 15, b = idx & 31;
                    xn[(gate * 16 + jj) * 33 + b] = g_xproj[xt + (gate * 256 + j0 + jj) * BB + b0 + b];
                }
                for (int idx = s; idx < 512; idx += 128) {
                    int f = idx >> 5, b = idx & 31;
                    xn[(64 + f) * 33 + b] = g_xproj[xt + (1024 + f) * BB + b0 + b];
                }
            }
            // ---- fre matvec: 32b x 16f, 1b x 4f per thread ----
            const int fb = s >> 2, f0 = (s & 3) * 4;
            const float* up = U_s + 64 + f0;
            float fa0 = 0.f, fa1 = 0.f, fa2 = 0.f, fa3 = 0.f;
#pragma unroll 4
            for (int k = 0; k < 256; k++) {
                float hk = h_s[k * 36 + fb];
                float4 uv = *(const float4*)(up + k * 80);
                fa0 += hk * uv.x; fa1 += hk * uv.y; fa2 += hk * uv.z; fa3 += hk * uv.w;
            }
            gt_s[(64 + f0 + 0) * 33 + fb] = fa0;
            gt_s[(64 + f0 + 1) * 33 + fb] = fa1;
            gt_s[(64 + f0 + 2) * 33 + fb] = fa2;
            gt_s[(64 + f0 + 3) * 33 + fb] = fa3;
        }
        __syncthreads();

        // ---- consumer: S update (registers) + h output ----
        float* hout = &g_h[(t & 1) ^ 1][0];
        const float* ret = re_t + t * 16;
        const float* imt = im_t + t * 16;
        float hres[2];
#pragma unroll
        for (int p = 0; p < 2; p++) {
            const int b = c_b2 + p;
            float gi  = hsig(gt_s[(     c_jj) * 33 + b] + xc[(     c_jj) * 33 + b]);
            float ste = hsig(gt_s[(16 + c_jj) * 33 + b] + xc[(16 + c_jj) * 33 + b]);
            float cg  = gi * ftanh(gt_s[(32 + c_jj) * 33 + b] + xc[(32 + c_jj) * 33 + b]);
            float o   = hsig(gt_s[(48 + c_jj) * 33 + b] + xc[(48 + c_jj) * 33 + b]);
            float Aa = 0.f;
#pragma unroll
            for (int f = 0; f < 16; f++) {
                float fre = hsig(gt_s[(64 + f) * 33 + b] + xc[(64 + f) * 33 + b]);
                float fv = ste * fre;
                float nr = fv * Sre[p][f] + cg * ret[f];
                float ni = fv * Sim[p][f] + cg * imt[f];
                Sre[p][f] = nr; Sim[p][f] = ni;
                Aa += (nr * nr + ni * ni) * Ua_s[f];
            }
            float a = ftanh(Aa + ba_s[c_jj]);
            hres[p] = o * a;
        }
        __stcg((float2*)&hout[(j0 + c_jj) * 256 + b0 + c_b2], make_float2(hres[0], hres[1]));

        // ---- grid barrier ----
        __threadfence();
        __syncthreads();
        if (tid == 0) {
            atomicAdd(&g_bar, 1u);
            const unsigned target = 128u * (unsigned)(t + 1);
            while (*(volatile unsigned*)&g_bar < target) { }
        }
        __syncthreads();
    }

    // ---- output head (CTA 0): final h is in g_h[0] ----
    if (blockIdx.x == 0) {
        const int b = tid;
        const float* h = &g_h[0][0];
        float s = 0.f;
#pragma unroll 8
        for (int j = 0; j < 256; j++) s += __ldcg(&h[j * 256 + b]) * W_p[j];
        float p = s + b_p[0];
        out[b] = p * fc_w[0] + fc_b[0];
    }
}

// ---------------- launch ----------------
extern "C" void kernel_launch(void* const* d_in, const int* in_sizes, int n_in,
                              void* d_out, int out_size)
{
    const float* sig  = (const float*)d_in[0];
    const float* met  = (const float*)d_in[1];
    const float* Wis  = (const float*)d_in[2];
    const float* Wss  = (const float*)d_in[3];
    const float* Wfs  = (const float*)d_in[4];
    const float* Wcs  = (const float*)d_in[5];
    const float* Wos  = (const float*)d_in[6];
    const float* Wim  = (const float*)d_in[7];
    const float* Wsm  = (const float*)d_in[8];
    const float* Wfm  = (const float*)d_in[9];
    const float* Wcm  = (const float*)d_in[10];
    const float* Wom  = (const float*)d_in[11];
    const float* U_i  = (const float*)d_in[12];
    const float* b_i  = (const float*)d_in[13];
    const float* U_ste= (const float*)d_in[14];
    const float* b_ste= (const float*)d_in[15];
    const float* U_fre= (const float*)d_in[16];
    const float* b_fre= (const float*)d_in[17];
    const float* U_c  = (const float*)d_in[18];
    const float* b_c  = (const float*)d_in[19];
    const float* U_o  = (const float*)d_in[20];
    const float* b_o  = (const float*)d_in[21];
    const float* U_a  = (const float*)d_in[22];
    const float* b_a  = (const float*)d_in[23];
    const float* W_p  = (const float*)d_in[24];
    const float* b_p  = (const float*)d_in[25];
    const float* fc_w = (const float*)d_in[26];
    const float* fc_b = (const float*)d_in[27];
    float* out = (float*)d_out;

    cudaFuncSetAttribute(persist_kernel, cudaFuncAttributeMaxDynamicSharedMemorySize,
                         PS_TOTAL * 4);

    init_kernel<<<1, 1>>>();
    proj_kernel<<<dim3(17, 4, 128), 128>>>(sig, met, Wis, Wss, Wfs, Wcs, Wos,
                                           Wim, Wsm, Wfm, Wcm, Wom,
                                           b_i, b_ste, b_fre, b_c, b_o);
    persist_kernel<<<128, 256, PS_TOTAL * 4>>>(U_i, U_ste, U_c, U_o, U_fre, U_a, b_a,
                                               W_p, b_p, fc_w, fc_b, out);
}